// round 12
// baseline (speedup 1.0000x reference)
#include <cuda_runtime.h>
#include <climits>

#define Bn 64
#define Hn 512
#define Wn 512
#define HWn (Hn * Wn)
#define HW4 (HWn / 4)
#define BLOCKS_PER_BATCH 128          // 4 rows per block
#define GRID (Bn * BLOCKS_PER_BATCH)  // 8192

// Per-block partials — fully overwritten every launch before being read.
// Counter self-resets (elected warp zeroes it): deterministic across replays.
__device__ float    g_ps1[GRID];
__device__ float    g_ps2[GRID];
__device__ unsigned g_pflags[GRID];   // 8 bits: row r (0..3) -> bits 2r (cup), 2r+1 (disc)
__device__ unsigned g_count[Bn];

__global__ void __launch_bounds__(256) cdr_fused_kernel(const float* __restrict__ x,
                                                        float* __restrict__ out) {
    const int b    = blockIdx.x >> 7;     // batch
    const int quad = blockIdx.x & 127;    // group of 4 rows
    const int tid  = threadIdx.x;
    const int rsel = tid >> 7;            // 0: rows {4q,4q+1}, 1: rows {4q+2,4q+3}
    const int c4   = tid & 127;
    const int rA   = quad * 4 + rsel * 2;

    // ---- Phase 1: 6 front-batched coalesced LDG.128 (L2-only, zero reuse) ----
    const float4* p = (const float4*)x;
    const size_t base4 = (((size_t)b * 3 * HWn + (size_t)rA * Wn) >> 2) + (size_t)c4;
    float4 v0a = __ldcg(p + base4);
    float4 v1a = __ldcg(p + base4 + HW4);
    float4 v2a = __ldcg(p + base4 + 2 * HW4);
    float4 v0b = __ldcg(p + base4 + 128);          // row rA+1
    float4 v1b = __ldcg(p + base4 + HW4 + 128);
    float4 v2b = __ldcg(p + base4 + 2 * HW4 + 128);

    float s1 = 0.f, s2 = 0.f;
    bool anyA1 = false, anyA2 = false, anyB1 = false, anyB2 = false;

    const float* f0 = (const float*)&v0a;
    const float* f1 = (const float*)&v1a;
    const float* f2 = (const float*)&v2a;
    const float* h0 = (const float*)&v0b;
    const float* h1 = (const float*)&v1b;
    const float* h2 = (const float*)&v2b;

#pragma unroll
    for (int k = 0; k < 4; k++) {
        float a0 = f0[k], a1 = f1[k], a2 = f2[k];
        float m01 = fmaxf(a0, a1);
        bool  l2  = a2 > m01;
        bool  l1  = (a1 > a0) && !l2;
        anyA1 |= l1;
        anyA2 |= l2;
        float e0  = __expf(a0 - a1);
        float e2  = __expf(a2 - a1);
        float inv = __fdividef(1.0f, e0 + 1.0f + e2);
        s1 += inv;        // p(cup)
        s2 += e2 * inv;   // p(disc)
    }
#pragma unroll
    for (int k = 0; k < 4; k++) {
        float a0 = h0[k], a1 = h1[k], a2 = h2[k];
        float m01 = fmaxf(a0, a1);
        bool  l2  = a2 > m01;
        bool  l1  = (a1 > a0) && !l2;
        anyB1 |= l1;
        anyB2 |= l2;
        float e0  = __expf(a0 - a1);
        float e2  = __expf(a2 - a1);
        float inv = __fdividef(1.0f, e0 + 1.0f + e2);
        s1 += inv;
        s2 += e2 * inv;
    }

    // ---- Phase 2: deterministic in-warp reduction ----
#pragma unroll
    for (int o = 16; o > 0; o >>= 1) {
        s1 += __shfl_xor_sync(0xFFFFFFFFu, s1, o);
        s2 += __shfl_xor_sync(0xFFFFFFFFu, s2, o);
    }
    // per-warp flags for its two rows (row rA -> bits 0/1, row rA+1 -> bits 2/3)
    unsigned wf = (__any_sync(0xFFFFFFFFu, anyA1) ? 1u : 0u)
                | (__any_sync(0xFFFFFFFFu, anyA2) ? 2u : 0u)
                | (__any_sync(0xFFFFFFFFu, anyB1) ? 4u : 0u)
                | (__any_sync(0xFFFFFFFFu, anyB2) ? 8u : 0u);

    __shared__ float    sw1[8], sw2[8];
    __shared__ unsigned swf[8];
    const int wid = tid >> 5, lid = tid & 31;
    if (lid == 0) { sw1[wid] = s1; sw2[wid] = s2; swf[wid] = wf; }
    __syncthreads();

    // 7 of 8 warps retire immediately — their SM slots go to the next block's loads.
    if (wid != 0) return;

    // ---- Phase 3: warp 0 only, warp-synchronous from here ----
    float pv1 = (lid < 8) ? sw1[lid] : 0.f;
    float pv2 = (lid < 8) ? sw2[lid] : 0.f;
#pragma unroll
    for (int o = 4; o > 0; o >>= 1) {
        pv1 += __shfl_xor_sync(0xFFFFFFFFu, pv1, o);
        pv2 += __shfl_xor_sync(0xFFFFFFFFu, pv2, o);
    }

    int lastFlag = 0;
    if (lid == 0) {
        // warps 0-3 handled rows {4q,4q+1} (bits 0-3), warps 4-7 rows {4q+2,4q+3}.
        unsigned fLo = swf[0] | swf[1] | swf[2] | swf[3];
        unsigned fHi = swf[4] | swf[5] | swf[6] | swf[7];
        unsigned fw  = (fLo & 0xFu) | ((fHi & 0xFu) << 4);
        g_ps1[blockIdx.x]    = pv1;
        g_ps2[blockIdx.x]    = pv2;
        g_pflags[blockIdx.x] = fw;
        __threadfence();
        lastFlag = (atomicAdd(&g_count[b], 1u) == BLOCKS_PER_BATCH - 1);
    }
    lastFlag = __shfl_sync(0xFFFFFFFFu, lastFlag, 0);
    if (!lastFlag) return;

    // ---- Phase 4: elected warp finalizes batch b (128 partials, 4 per lane) ----
    float t1 = 0.f, t2 = 0.f;
    int mn1 = INT_MAX, mx1 = -1, mn2 = INT_MAX, mx2 = -1;
#pragma unroll
    for (int j = 0; j < 4; j++) {
        int e   = lid + 32 * j;                  // block index within batch
        int idx = b * BLOCKS_PER_BATCH + e;
        t1 += __ldcg(&g_ps1[idx]);
        t2 += __ldcg(&g_ps2[idx]);
        unsigned fl = __ldcg(&g_pflags[idx]);
#pragma unroll
        for (int r = 0; r < 4; r++) {
            int rr = e * 4 + r;
            if (fl & (1u << (2 * r)))     { mn1 = min(mn1, rr); mx1 = max(mx1, rr); }
            if (fl & (1u << (2 * r + 1))) { mn2 = min(mn2, rr); mx2 = max(mx2, rr); }
        }
    }
#pragma unroll
    for (int o = 16; o > 0; o >>= 1) {
        t1  += __shfl_xor_sync(0xFFFFFFFFu, t1, o);
        t2  += __shfl_xor_sync(0xFFFFFFFFu, t2, o);
        mn1  = min(mn1, __shfl_xor_sync(0xFFFFFFFFu, mn1, o));
        mx1  = max(mx1, __shfl_xor_sync(0xFFFFFFFFu, mx1, o));
        mn2  = min(mn2, __shfl_xor_sync(0xFFFFFFFFu, mn2, o));
        mx2  = max(mx2, __shfl_xor_sync(0xFFFFFFFFu, mx2, o));
    }

    if (lid == 0) {
        const float inv_hw = 1.0f / (float)HWn;
        float cup_mean  = t1 * inv_hw;
        float disc_mean = t2 * inv_hw;
        float hcup  = (mx1 >= 0) ? (float)(mx1 - mn1) : 0.0f;
        float hdisc = (mx2 >= 0) ? (float)(mx2 - mn2) : 0.0f;
        float cdr = hcup / (hdisc + 1e-6f);
        out[b * 5 + 0] = cdr;
        out[b * 5 + 1] = disc_mean;
        out[b * 5 + 2] = cup_mean;
        out[b * 5 + 3] = disc_mean;
        out[b * 5 + 4] = cup_mean;
        g_count[b] = 0;   // self-reset: deterministic across graph replays
    }
}

extern "C" void kernel_launch(void* const* d_in, const int* in_sizes, int n_in,
                              void* d_out, int out_size) {
    const float* x = (const float*)d_in[0];
    float* out = (float*)d_out;
    (void)in_sizes; (void)n_in; (void)out_size;

    cdr_fused_kernel<<<GRID, 256>>>(x, out);
}

// round 13
// speedup vs baseline: 1.0172x; 1.0172x over previous
#include <cuda_runtime.h>
#include <climits>

#define Bn 64
#define Hn 512
#define Wn 512
#define HWn (Hn * Wn)
#define HW4 (HWn / 4)
#define BLOCKS_PER_BATCH 128          // 4 rows per block
#define GRID (Bn * BLOCKS_PER_BATCH)  // 8192

// Per-block partials — fully overwritten every launch before being read.
// Counter self-resets (elected warp zeroes it): deterministic across replays.
__device__ float    g_ps1[GRID];
__device__ float    g_ps2[GRID];
__device__ unsigned g_pflags[GRID];   // 8 bits: row r (0..3) -> bits 2r (cup), 2r+1 (disc)
__device__ unsigned g_count[Bn];

__global__ void __launch_bounds__(256) cdr_fused_kernel(const float* __restrict__ x,
                                                        float* __restrict__ out) {
    const int b    = blockIdx.x >> 7;     // batch
    const int quad = blockIdx.x & 127;    // group of 4 rows
    const int tid  = threadIdx.x;
    const int rsel = tid >> 7;            // 0: rows {4q,4q+1}, 1: rows {4q+2,4q+3}
    const int c4   = tid & 127;
    const int rA   = quad * 4 + rsel * 2;

    // ---- Phase 1: 6 front-batched coalesced LDG.128 (evict-first: zero reuse) ----
    const float4* p = (const float4*)x;
    const size_t base4 = (((size_t)b * 3 * HWn + (size_t)rA * Wn) >> 2) + (size_t)c4;
    float4 v0a = __ldcs(p + base4);
    float4 v1a = __ldcs(p + base4 + HW4);
    float4 v2a = __ldcs(p + base4 + 2 * HW4);
    float4 v0b = __ldcs(p + base4 + 128);          // row rA+1
    float4 v1b = __ldcs(p + base4 + HW4 + 128);
    float4 v2b = __ldcs(p + base4 + 2 * HW4 + 128);

    float s1 = 0.f, s2 = 0.f;
    bool anyA1 = false, anyA2 = false, anyB1 = false, anyB2 = false;

    const float* f0 = (const float*)&v0a;
    const float* f1 = (const float*)&v1a;
    const float* f2 = (const float*)&v2a;
    const float* h0 = (const float*)&v0b;
    const float* h1 = (const float*)&v1b;
    const float* h2 = (const float*)&v2b;

#pragma unroll
    for (int k = 0; k < 4; k++) {
        float a0 = f0[k], a1 = f1[k], a2 = f2[k];
        float m01 = fmaxf(a0, a1);
        bool  l2  = a2 > m01;
        bool  l1  = (a1 > a0) && !l2;
        anyA1 |= l1;
        anyA2 |= l2;
        float e0  = __expf(a0 - a1);
        float e2  = __expf(a2 - a1);
        float inv = __fdividef(1.0f, e0 + 1.0f + e2);
        s1 += inv;        // p(cup)
        s2 += e2 * inv;   // p(disc)
    }
#pragma unroll
    for (int k = 0; k < 4; k++) {
        float a0 = h0[k], a1 = h1[k], a2 = h2[k];
        float m01 = fmaxf(a0, a1);
        bool  l2  = a2 > m01;
        bool  l1  = (a1 > a0) && !l2;
        anyB1 |= l1;
        anyB2 |= l2;
        float e0  = __expf(a0 - a1);
        float e2  = __expf(a2 - a1);
        float inv = __fdividef(1.0f, e0 + 1.0f + e2);
        s1 += inv;
        s2 += e2 * inv;
    }

    // ---- Phase 2: deterministic in-warp reduction ----
#pragma unroll
    for (int o = 16; o > 0; o >>= 1) {
        s1 += __shfl_xor_sync(0xFFFFFFFFu, s1, o);
        s2 += __shfl_xor_sync(0xFFFFFFFFu, s2, o);
    }
    // per-warp flags for its two rows (row rA -> bits 0/1, row rA+1 -> bits 2/3)
    unsigned wf = (__any_sync(0xFFFFFFFFu, anyA1) ? 1u : 0u)
                | (__any_sync(0xFFFFFFFFu, anyA2) ? 2u : 0u)
                | (__any_sync(0xFFFFFFFFu, anyB1) ? 4u : 0u)
                | (__any_sync(0xFFFFFFFFu, anyB2) ? 8u : 0u);

    __shared__ float    sw1[8], sw2[8];
    __shared__ unsigned swf[8];
    const int wid = tid >> 5, lid = tid & 31;
    if (lid == 0) { sw1[wid] = s1; sw2[wid] = s2; swf[wid] = wf; }
    __syncthreads();

    // 7 of 8 warps retire immediately — their SM slots go to the next block's loads.
    if (wid != 0) return;

    // ---- Phase 3: warp 0 only, warp-synchronous from here ----
    float pv1 = (lid < 8) ? sw1[lid] : 0.f;
    float pv2 = (lid < 8) ? sw2[lid] : 0.f;
#pragma unroll
    for (int o = 4; o > 0; o >>= 1) {
        pv1 += __shfl_xor_sync(0xFFFFFFFFu, pv1, o);
        pv2 += __shfl_xor_sync(0xFFFFFFFFu, pv2, o);
    }

    int lastFlag = 0;
    if (lid == 0) {
        // warps 0-3 handled rows {4q,4q+1} (bits 0-3), warps 4-7 rows {4q+2,4q+3}.
        unsigned fLo = swf[0] | swf[1] | swf[2] | swf[3];
        unsigned fHi = swf[4] | swf[5] | swf[6] | swf[7];
        unsigned fw  = (fLo & 0xFu) | ((fHi & 0xFu) << 4);
        g_ps1[blockIdx.x]    = pv1;
        g_ps2[blockIdx.x]    = pv2;
        g_pflags[blockIdx.x] = fw;
        __threadfence();
        lastFlag = (atomicAdd(&g_count[b], 1u) == BLOCKS_PER_BATCH - 1);
    }
    lastFlag = __shfl_sync(0xFFFFFFFFu, lastFlag, 0);
    if (!lastFlag) return;

    // ---- Phase 4: elected warp finalizes batch b (128 partials, 4 per lane) ----
    float t1 = 0.f, t2 = 0.f;
    int mn1 = INT_MAX, mx1 = -1, mn2 = INT_MAX, mx2 = -1;
#pragma unroll
    for (int j = 0; j < 4; j++) {
        int e   = lid + 32 * j;                  // block index within batch
        int idx = b * BLOCKS_PER_BATCH + e;
        t1 += __ldcg(&g_ps1[idx]);
        t2 += __ldcg(&g_ps2[idx]);
        unsigned fl = __ldcg(&g_pflags[idx]);
#pragma unroll
        for (int r = 0; r < 4; r++) {
            int rr = e * 4 + r;
            if (fl & (1u << (2 * r)))     { mn1 = min(mn1, rr); mx1 = max(mx1, rr); }
            if (fl & (1u << (2 * r + 1))) { mn2 = min(mn2, rr); mx2 = max(mx2, rr); }
        }
    }
#pragma unroll
    for (int o = 16; o > 0; o >>= 1) {
        t1  += __shfl_xor_sync(0xFFFFFFFFu, t1, o);
        t2  += __shfl_xor_sync(0xFFFFFFFFu, t2, o);
        mn1  = min(mn1, __shfl_xor_sync(0xFFFFFFFFu, mn1, o));
        mx1  = max(mx1, __shfl_xor_sync(0xFFFFFFFFu, mx1, o));
        mn2  = min(mn2, __shfl_xor_sync(0xFFFFFFFFu, mn2, o));
        mx2  = max(mx2, __shfl_xor_sync(0xFFFFFFFFu, mx2, o));
    }

    if (lid == 0) {
        const float inv_hw = 1.0f / (float)HWn;
        float cup_mean  = t1 * inv_hw;
        float disc_mean = t2 * inv_hw;
        float hcup  = (mx1 >= 0) ? (float)(mx1 - mn1) : 0.0f;
        float hdisc = (mx2 >= 0) ? (float)(mx2 - mn2) : 0.0f;
        float cdr = hcup / (hdisc + 1e-6f);
        out[b * 5 + 0] = cdr;
        out[b * 5 + 1] = disc_mean;
        out[b * 5 + 2] = cup_mean;
        out[b * 5 + 3] = disc_mean;
        out[b * 5 + 4] = cup_mean;
        g_count[b] = 0;   // self-reset: deterministic across graph replays
    }
}

extern "C" void kernel_launch(void* const* d_in, const int* in_sizes, int n_in,
                              void* d_out, int out_size) {
    const float* x = (const float*)d_in[0];
    float* out = (float*)d_out;
    (void)in_sizes; (void)n_in; (void)out_size;

    cdr_fused_kernel<<<GRID, 256>>>(x, out);
}